// round 5
// baseline (speedup 1.0000x reference)
#include <cuda_runtime.h>
#include <cstdint>
#include <cstddef>

// ---------------------------------------------------------------------------
// WaveNet gated residual block, single fused kernel, tf32 mma.sync (sm_103
// baseline PTX — tcgen05 unavailable under compute_103).
//
// Per CTA (128-token tile, 8 warps, occ 1, 224KB smem):
//   gate pass p=0,1 : acc[128,256] = A x Wg_packed(p)^T  (tanh/sig interleaved
//                     by 8-col groups -> same thread holds both halves)
//                     epilogue: m = tanh(t+bt)*sig(s+bs) -> smem m region
//   out  pass0      : [128,256] = m x Wo[res 0..127 | skip 0..127]^T
//   out  pass1      : [128,128] = m x Wo[skip 128..255]^T
//
// All operands tf32-rounded ahead of time (prep kernel) and stored
// k-pair-interleaved ((k,k+4) adjacent) with (row&3)-XOR 16B swizzle so
// fragment loads are LDS.64, conflict-free per half-warp.
// ---------------------------------------------------------------------------

#define DEVFN __device__ __forceinline__

// smem float offsets
static constexpr int MOFF = 0;         // m region: 128 x 256 floats (128 KB)
static constexpr int AOFF = 32768;     // A stages: 2 x 4096 floats (32 KB)
static constexpr int BOFF = 40960;     // B stages: 2 x 8192 floats (64 KB)
static constexpr int SMEM_FLOATS = 57344;
static constexpr int SMEM_BYTES = SMEM_FLOATS * 4;   // 229376 <= 232448

__device__ float wscratch[896 * 256];      // packed tf32 weights (896 KB)
__device__ float xscratch[131072 * 128];   // tf32-rounded, k-packed x (64 MB)

// ------------------------------- helpers -----------------------------------
DEVFN uint32_t smaddr(const void* p) {
    uint32_t a;
    asm("{ .reg .u64 t; cvta.to.shared.u64 t, %1; cvt.u32.u64 %0, t; }" : "=r"(a) : "l"(p));
    return a;
}
DEVFN uint32_t tf32r(float x) { uint32_t u; asm("cvt.rna.tf32.f32 %0, %1;" : "=r"(u) : "f"(x)); return u; }
DEVFN float ex2f(float x) { float y; asm("ex2.approx.ftz.f32 %0, %1;" : "=f"(y) : "f"(x)); return y; }
DEVFN float rcpf(float x) { float y; asm("rcp.approx.ftz.f32 %0, %1;" : "=f"(y) : "f"(x)); return y; }

// gated activation: tanh(a)*sigmoid(b) = (u-1)*v / ((u+1)*(v+1)),
// u = e^{2a}, v = e^{b}; clamped (saturation-safe), tf32-rounded.
DEVFN float gatem(float a, float b) {
    a = fminf(fmaxf(a, -15.f), 15.f);
    b = fminf(fmaxf(b, -30.f), 30.f);
    float u = ex2f(a * 2.8853900817779268f);
    float v = ex2f(b * 1.4426950408889634f);
    float m = (u - 1.f) * v * rcpf((u + 1.f) * (v + 1.f));
    return __uint_as_float(tf32r(m));
}

DEVFN void cpa16(uint32_t dst, const void* src, int sz) {
    asm volatile("cp.async.cg.shared.global [%0], [%1], 16, %2;"
                 :: "r"(dst), "l"(src), "r"(sz) : "memory");
}
DEVFN void cpcommit() { asm volatile("cp.async.commit_group;" ::: "memory"); }
#define CPWAIT(n) asm volatile("cp.async.wait_group %0;" :: "n"(n) : "memory")

// m16n8k8 tf32 mma, row.col, f32 accum
DEVFN void mma8(float* d, const uint32_t* a, const uint32_t* b) {
    asm("mma.sync.aligned.m16n8k8.row.col.f32.tf32.tf32.f32 "
        "{%0,%1,%2,%3}, {%4,%5,%6,%7}, {%8,%9}, {%0,%1,%2,%3};"
        : "+f"(d[0]), "+f"(d[1]), "+f"(d[2]), "+f"(d[3])
        : "r"(a[0]), "r"(a[1]), "r"(a[2]), "r"(a[3]), "r"(b[0]), "r"(b[1]));
}

// ------------------------------ prep kernel --------------------------------
// wscratch rows:
//   0..511   gate passes: row = p*256 + pp; pp interleaves [tanh c..c+7 | sig c..c+7]
//   512..767 out pass0: res 0..127 | skip 0..127
//   768..895 out pass1: skip 128..255
// Every row: 256 k-values stored pair-interleaved: q(k)=(k&~7)+((k&3)<<1)+((k>>2)&1)
// xscratch: per token 128 floats, same q-packing, tf32-rounded.
__global__ void __launch_bounds__(256)
prep_kernel(const float* __restrict__ wt, const float* __restrict__ ws,
            const float* __restrict__ wr, const float* __restrict__ wk,
            const float* __restrict__ x) {
    int bid = blockIdx.x, tid = threadIdx.x;
    if (bid < 896) {
        int idx = bid * 256 + tid;
        int row = idx >> 8, k = idx & 255;
        float v;
        if (row < 512) {
            int p = row >> 8, pp = row & 255;
            int is_sig = (pp >> 3) & 1;
            int C = p * 128 + ((pp >> 4) << 3) + (pp & 7);
            int src = ((k >> 7) * 128 + (k & 127)) * 256 + C;
            v = is_sig ? ws[src] : wt[src];
        } else if (row < 768) {
            int j = row - 512;
            v = (j < 128) ? wr[k * 128 + j] : wk[k * 256 + (j - 128)];
        } else {
            v = wk[k * 256 + 128 + (row - 768)];
        }
        int q = (k & ~7) + ((k & 3) << 1) + ((k >> 2) & 1);
        wscratch[row * 256 + q] = __uint_as_float(tf32r(v));
    } else {
        // x packing: one 8-float group per thread
        size_t g = (size_t)(bid - 896) * 256 + tid;   // < 2097152
        const float* src = x + g * 8;
        float4 lo = *(const float4*)src;
        float4 hi = *(const float4*)(src + 4);
        float4 o0 = make_float4(__uint_as_float(tf32r(lo.x)), __uint_as_float(tf32r(hi.x)),
                                __uint_as_float(tf32r(lo.y)), __uint_as_float(tf32r(hi.y)));
        float4 o1 = make_float4(__uint_as_float(tf32r(lo.z)), __uint_as_float(tf32r(hi.z)),
                                __uint_as_float(tf32r(lo.w)), __uint_as_float(tf32r(hi.w)));
        float* dst = xscratch + g * 8;
        *(float4*)dst = o0;
        *(float4*)(dst + 4) = o1;
    }
}

// ------------------------------ fused kernel -------------------------------
__global__ void __launch_bounds__(256, 1)
fused_kernel(const float* __restrict__ x,
             const float* __restrict__ bt, const float* __restrict__ bs,
             const float* __restrict__ br, const float* __restrict__ bk,
             float* __restrict__ out) {
    extern __shared__ float sm[];
    uint32_t sb = smaddr(sm);
    int tid = threadIdx.x, wid = tid >> 5, lid = tid & 31;
    int mwarp = wid >> 2, nwarp = wid & 3;
    int r0 = lid >> 2, c0 = lid & 3;
    int tile = blockIdx.x;
    long g0 = (long)tile * 128;
    bool head = (tile & 127) == 0;          // first tile in a batch row (T=16384)

    float acc[4][8][4];

    // ---- async loaders (per kc chunk of 32 k) ----
    auto loadA = [&](int kc, int st) {      // 128 rows x 8 x 16B
#pragma unroll
        for (int i = 0; i < 4; ++i) {
            int idx = tid + i * 256;
            int row = idx >> 3, b = idx & 7;
            const float* src = xscratch;
            int sz = 16;
            if (kc < 4) {
                if (head && row < 4) sz = 0;
                else src = xscratch + (g0 + row - 4) * 128 + (kc & 3) * 32 + b * 4;
            } else {
                src = xscratch + (g0 + row) * 128 + (kc & 3) * 32 + b * 4;
            }
            uint32_t dst = sb + (uint32_t)(AOFF + st * 4096 + row * 32 + 4 * (b ^ ((row & 3) << 1))) * 4;
            cpa16(dst, src, sz);
        }
    };
    auto loadB256 = [&](const float* wb, int kc, int st) {   // 256 rows
#pragma unroll
        for (int i = 0; i < 8; ++i) {
            int idx = tid + i * 256;
            int n = idx >> 3, b = idx & 7;
            const float* src = wb + n * 256 + kc * 32 + b * 4;
            uint32_t dst = sb + (uint32_t)(BOFF + st * 8192 + n * 32 + 4 * (b ^ ((n & 3) << 1))) * 4;
            cpa16(dst, src, 16);
        }
    };
    auto loadB128 = [&](const float* wb, int kc, int st) {   // 128 rows
#pragma unroll
        for (int i = 0; i < 4; ++i) {
            int idx = tid + i * 256;
            int n = idx >> 3, b = idx & 7;
            const float* src = wb + n * 256 + kc * 32 + b * 4;
            uint32_t dst = sb + (uint32_t)(BOFF + st * 8192 + n * 32 + 4 * (b ^ ((n & 3) << 1))) * 4;
            cpa16(dst, src, 16);
        }
    };

    auto zacc = [&]() {
#pragma unroll
        for (int i = 0; i < 4; ++i)
#pragma unroll
            for (int j = 0; j < 8; ++j)
#pragma unroll
                for (int q = 0; q < 4; ++q) acc[i][j][q] = 0.f;
    };

    // ---- compute bodies ----
    auto gate_compute = [&](int kc) {       // A from A-stage, B 256 rows
        int ast = AOFF + (kc & 1) * 4096;
        int bst = BOFF + (kc & 1) * 8192;
#pragma unroll
        for (int ks = 0; ks < 4; ++ks) {
            uint32_t a[4][4];
#pragma unroll
            for (int mf = 0; mf < 4; ++mf) {
                int row = mwarp * 64 + mf * 16 + r0;
                int o = ((ks ^ (row & 3)) << 3) + 2 * c0;
                float2 lo = *(float2*)&sm[ast + row * 32 + o];
                float2 hi = *(float2*)&sm[ast + (row + 8) * 32 + o];
                a[mf][0] = __float_as_uint(lo.x); a[mf][1] = __float_as_uint(hi.x);
                a[mf][2] = __float_as_uint(lo.y); a[mf][3] = __float_as_uint(hi.y);
            }
#pragma unroll
            for (int nf = 0; nf < 8; ++nf) {
                int n = nwarp * 64 + nf * 8 + r0;
                float2 bv = *(float2*)&sm[bst + n * 32 + ((ks ^ (n & 3)) << 3) + 2 * c0];
                uint32_t b[2] = {__float_as_uint(bv.x), __float_as_uint(bv.y)};
#pragma unroll
                for (int mf = 0; mf < 4; ++mf) mma8(acc[mf][nf], a[mf], b);
            }
        }
    };
    auto out_compute256 = [&](int kc) {     // A from m region, B 256 rows
        int bst = BOFF + (kc & 1) * 8192;
#pragma unroll
        for (int ks = 0; ks < 4; ++ks) {
            uint32_t a[4][4];
#pragma unroll
            for (int mf = 0; mf < 4; ++mf) {
                int row = mwarp * 64 + mf * 16 + r0;
                int o = kc * 32 + ((ks ^ (row & 3)) << 3) + 2 * c0;
                float2 lo = *(float2*)&sm[MOFF + row * 256 + o];
                float2 hi = *(float2*)&sm[MOFF + (row + 8) * 256 + o];
                a[mf][0] = __float_as_uint(lo.x); a[mf][1] = __float_as_uint(hi.x);
                a[mf][2] = __float_as_uint(lo.y); a[mf][3] = __float_as_uint(hi.y);
            }
#pragma unroll
            for (int nf = 0; nf < 8; ++nf) {
                int n = nwarp * 64 + nf * 8 + r0;
                float2 bv = *(float2*)&sm[bst + n * 32 + ((ks ^ (n & 3)) << 3) + 2 * c0];
                uint32_t b[2] = {__float_as_uint(bv.x), __float_as_uint(bv.y)};
#pragma unroll
                for (int mf = 0; mf < 4; ++mf) mma8(acc[mf][nf], a[mf], b);
            }
        }
    };
    auto out_compute128 = [&](int kc) {     // A from m region, B 128 rows
        int bst = BOFF + (kc & 1) * 8192;
#pragma unroll
        for (int ks = 0; ks < 4; ++ks) {
            uint32_t a[4][4];
#pragma unroll
            for (int mf = 0; mf < 4; ++mf) {
                int row = mwarp * 64 + mf * 16 + r0;
                int o = kc * 32 + ((ks ^ (row & 3)) << 3) + 2 * c0;
                float2 lo = *(float2*)&sm[MOFF + row * 256 + o];
                float2 hi = *(float2*)&sm[MOFF + (row + 8) * 256 + o];
                a[mf][0] = __float_as_uint(lo.x); a[mf][1] = __float_as_uint(hi.x);
                a[mf][2] = __float_as_uint(lo.y); a[mf][3] = __float_as_uint(hi.y);
            }
#pragma unroll
            for (int nf = 0; nf < 4; ++nf) {
                int n = nwarp * 32 + nf * 8 + r0;
                float2 bv = *(float2*)&sm[bst + n * 32 + ((ks ^ (n & 3)) << 3) + 2 * c0];
                uint32_t b[2] = {__float_as_uint(bv.x), __float_as_uint(bv.y)};
#pragma unroll
                for (int mf = 0; mf < 4; ++mf) mma8(acc[mf][nf], a[mf], b);
            }
        }
    };

    // ================= gate passes =================
#pragma unroll 1
    for (int p = 0; p < 2; ++p) {
        const float* wb = wscratch + p * 256 * 256;
        zacc();
        loadA(0, 0); loadB256(wb, 0, 0); cpcommit();
        loadA(1, 1); loadB256(wb, 1, 1); cpcommit();
#pragma unroll 1
        for (int kc = 0; kc < 8; ++kc) {
            CPWAIT(1);
            __syncthreads();
            gate_compute(kc);
            __syncthreads();
            if (kc < 6) { loadA(kc + 2, kc & 1); loadB256(wb, kc + 2, kc & 1); }
            cpcommit();
        }
        // epilogue: m -> smem m region (pass columns p*128 .. p*128+127)
#pragma unroll
        for (int mf = 0; mf < 4; ++mf) {
            int rA = mwarp * 64 + mf * 16 + r0;
            int xr = (rA & 3) << 3;
#pragma unroll
            for (int j = 0; j < 4; ++j) {
                int G = nwarp * 4 + j;
                int chb = p * 128 + G * 8 + 2 * c0;       // even channel
                float bt0 = __ldg(bt + chb), bt1 = __ldg(bt + chb + 1);
                float bs0 = __ldg(bs + chb), bs1 = __ldg(bs + chb + 1);
                float* At = acc[mf][2 * j];
                float* As = acc[mf][2 * j + 1];
                int e0 = 2 * c0, e1 = 2 * c0 + 1;
                int q0 = p * 128 + G * 8 + ((e0 & 3) << 1) + (e0 >> 2);
                int q1 = p * 128 + G * 8 + ((e1 & 3) << 1) + (e1 >> 2);
                sm[MOFF + rA * 256       + (q0 ^ xr)] = gatem(At[0] + bt0, As[0] + bs0);
                sm[MOFF + rA * 256       + (q1 ^ xr)] = gatem(At[1] + bt1, As[1] + bs1);
                sm[MOFF + (rA + 8) * 256 + (q0 ^ xr)] = gatem(At[2] + bt0, As[2] + bs0);
                sm[MOFF + (rA + 8) * 256 + (q1 ^ xr)] = gatem(At[3] + bt1, As[3] + bs1);
            }
        }
    }

    float* outR = out;                                // res  [131072,128]
    float* outK = out + (size_t)131072 * 128;         // skip [131072,256]

    // ================= out pass 0 (res | skip 0..127) =================
    {
        const float* wo = wscratch + 512 * 256;
        zacc();
        loadB256(wo, 0, 0); cpcommit();
        loadB256(wo, 1, 1); cpcommit();
#pragma unroll 1
        for (int kc = 0; kc < 8; ++kc) {
            CPWAIT(1);
            __syncthreads();        // first iter also fences m stores
            out_compute256(kc);
            __syncthreads();
            if (kc < 6) loadB256(wo, kc + 2, kc & 1);
            cpcommit();
        }
#pragma unroll
        for (int mf = 0; mf < 4; ++mf) {
            long row0 = g0 + mwarp * 64 + mf * 16 + r0, row1 = row0 + 8;
#pragma unroll
            for (int nf = 0; nf < 8; ++nf) {
                int pcol = nwarp * 64 + nf * 8 + 2 * c0;
                float* A = acc[mf][nf];
                if (pcol < 128) {
                    float b0 = __ldg(br + pcol), b1 = __ldg(br + pcol + 1);
                    float2 x0v = *(const float2*)(x + row0 * 128 + pcol);
                    float2 x1v = *(const float2*)(x + row1 * 128 + pcol);
                    *(float2*)(outR + row0 * 128 + pcol) =
                        make_float2(A[0] + b0 + x0v.x, A[1] + b1 + x0v.y);
                    *(float2*)(outR + row1 * 128 + pcol) =
                        make_float2(A[2] + b0 + x1v.x, A[3] + b1 + x1v.y);
                } else {
                    int ck = pcol - 128;
                    float b0 = __ldg(bk + ck), b1 = __ldg(bk + ck + 1);
                    *(float2*)(outK + row0 * 256 + ck) = make_float2(A[0] + b0, A[1] + b1);
                    *(float2*)(outK + row1 * 256 + ck) = make_float2(A[2] + b0, A[3] + b1);
                }
            }
        }
    }

    // ================= out pass 1 (skip 128..255) =================
    {
        const float* wo = wscratch + 768 * 256;
#pragma unroll
        for (int i = 0; i < 4; ++i)
#pragma unroll
            for (int j = 0; j < 4; ++j)
#pragma unroll
                for (int q = 0; q < 4; ++q) acc[i][j][q] = 0.f;
        loadB128(wo, 0, 0); cpcommit();
        loadB128(wo, 1, 1); cpcommit();
#pragma unroll 1
        for (int kc = 0; kc < 8; ++kc) {
            CPWAIT(1);
            __syncthreads();
            out_compute128(kc);
            __syncthreads();
            if (kc < 6) loadB128(wo, kc + 2, kc & 1);
            cpcommit();
        }
#pragma unroll
        for (int mf = 0; mf < 4; ++mf) {
            long row0 = g0 + mwarp * 64 + mf * 16 + r0, row1 = row0 + 8;
#pragma unroll
            for (int nf = 0; nf < 4; ++nf) {
                int ck = 128 + nwarp * 32 + nf * 8 + 2 * c0;
                float* A = acc[mf][nf];
                float b0 = __ldg(bk + ck), b1 = __ldg(bk + ck + 1);
                *(float2*)(outK + row0 * 256 + ck) = make_float2(A[0] + b0, A[1] + b1);
                *(float2*)(outK + row1 * 256 + ck) = make_float2(A[2] + b0, A[3] + b1);
            }
        }
    }
}

// ------------------------------- launch ------------------------------------
extern "C" void kernel_launch(void* const* d_in, const int* in_sizes, int n_in,
                              void* d_out, int out_size) {
    const float* x  = (const float*)d_in[0];
    const float* wt = (const float*)d_in[1];
    const float* bt = (const float*)d_in[2];
    const float* ws = (const float*)d_in[3];
    const float* bs = (const float*)d_in[4];
    const float* wr = (const float*)d_in[5];
    const float* br = (const float*)d_in[6];
    const float* wk = (const float*)d_in[7];
    const float* bk = (const float*)d_in[8];
    float* out = (float*)d_out;

    cudaFuncSetAttribute(fused_kernel,
                         cudaFuncAttributeMaxDynamicSharedMemorySize, SMEM_BYTES);

    prep_kernel<<<896 + 8192, 256>>>(wt, ws, wr, wk, x);
    fused_kernel<<<1024, 256, SMEM_BYTES>>>(x, bt, bs, br, bk, out);
}

// round 6
// speedup vs baseline: 1.1287x; 1.1287x over previous
#include <cuda_runtime.h>
#include <cstdint>
#include <cstddef>

// ---------------------------------------------------------------------------
// WaveNet gated residual block, single fused kernel, tf32 mma.sync (sm_103
// baseline PTX — tcgen05 unavailable under compute_103).
//
// Per CTA (128-token tile, 16 warps, 224KB smem):
//   gate pass p=0,1 : acc[128,256] = A x Wg_packed(p)^T  (tanh/sig interleaved
//                     by 8-col groups -> same thread holds both halves)
//                     epilogue: m = tanh(t+bt)*sig(s+bs) -> smem m region
//   out  pass0      : [128,256] = m x Wo[res 0..127 | skip 0..127]^T
//   out  pass1      : [128,128] = m x Wo[skip 128..255]^T
//
// Operands tf32-rounded ahead of time (prep kernel), stored k-pair-interleaved
// ((k,k+4) adjacent) with (row&3)-XOR 16B swizzle: fragment loads are LDS.64,
// conflict-free, and the XOR collapses to one per-ks constant per thread.
// ---------------------------------------------------------------------------

#define DEVFN __device__ __forceinline__

// smem float offsets
static constexpr int MOFF = 0;         // m region: 128 x 256 floats (128 KB)
static constexpr int AOFF = 32768;     // A stages: 2 x 4096 floats (32 KB)
static constexpr int BOFF = 40960;     // B stages: 2 x 8192 floats (64 KB)
static constexpr int SMEM_BYTES = 57344 * 4;   // 229376

__device__ float wscratch[896 * 256];      // packed tf32 weights (896 KB)
__device__ float xscratch[131072 * 128];   // tf32-rounded, k-packed x (64 MB)

// ------------------------------- helpers -----------------------------------
DEVFN uint32_t smaddr(const void* p) {
    uint32_t a;
    asm("{ .reg .u64 t; cvta.to.shared.u64 t, %1; cvt.u32.u64 %0, t; }" : "=r"(a) : "l"(p));
    return a;
}
DEVFN uint32_t tf32r(float x) { uint32_t u; asm("cvt.rna.tf32.f32 %0, %1;" : "=r"(u) : "f"(x)); return u; }
DEVFN float ex2f(float x) { float y; asm("ex2.approx.ftz.f32 %0, %1;" : "=f"(y) : "f"(x)); return y; }
DEVFN float rcpf(float x) { float y; asm("rcp.approx.ftz.f32 %0, %1;" : "=f"(y) : "f"(x)); return y; }

// gated activation: tanh(a)*sigmoid(b) = (u-1)*v / ((u+1)*(v+1)),
// u = e^{2a}, v = e^{b}; clamped (saturation-safe), tf32-rounded.
DEVFN float gatem(float a, float b) {
    a = fminf(fmaxf(a, -15.f), 15.f);
    b = fminf(fmaxf(b, -30.f), 30.f);
    float u = ex2f(a * 2.8853900817779268f);
    float v = ex2f(b * 1.4426950408889634f);
    float m = (u - 1.f) * v * rcpf((u + 1.f) * (v + 1.f));
    return __uint_as_float(tf32r(m));
}

DEVFN void cpa16(uint32_t dst, const void* src, int sz) {
    asm volatile("cp.async.cg.shared.global [%0], [%1], 16, %2;"
                 :: "r"(dst), "l"(src), "r"(sz) : "memory");
}
DEVFN void cpcommit() { asm volatile("cp.async.commit_group;" ::: "memory"); }
#define CPWAIT(n) asm volatile("cp.async.wait_group %0;" :: "n"(n) : "memory")

// m16n8k8 tf32 mma, row.col, f32 accum
DEVFN void mma8(float* d, const uint32_t* a, const uint32_t* b) {
    asm("mma.sync.aligned.m16n8k8.row.col.f32.tf32.tf32.f32 "
        "{%0,%1,%2,%3}, {%4,%5,%6,%7}, {%8,%9}, {%0,%1,%2,%3};"
        : "+f"(d[0]), "+f"(d[1]), "+f"(d[2]), "+f"(d[3])
        : "r"(a[0]), "r"(a[1]), "r"(a[2]), "r"(a[3]), "r"(b[0]), "r"(b[1]));
}

// ------------------------------ prep kernel --------------------------------
// wscratch rows:
//   0..511   gate passes: row = p*256 + pp; pp interleaves [tanh c..c+7 | sig c..c+7]
//   512..767 out pass0: res 0..127 | skip 0..127
//   768..895 out pass1: skip 128..255
// Every row: 256 k-values pair-interleaved: q(k)=(k&~7)+((k&3)<<1)+((k>>2)&1)
// xscratch: per token 128 floats, same q-packing, tf32-rounded.
__global__ void __launch_bounds__(256)
prep_kernel(const float* __restrict__ wt, const float* __restrict__ ws,
            const float* __restrict__ wr, const float* __restrict__ wk,
            const float* __restrict__ x) {
    int bid = blockIdx.x, tid = threadIdx.x;
    if (bid < 896) {
        int idx = bid * 256 + tid;
        int row = idx >> 8, k = idx & 255;
        float v;
        if (row < 512) {
            int p = row >> 8, pp = row & 255;
            int is_sig = (pp >> 3) & 1;
            int C = p * 128 + ((pp >> 4) << 3) + (pp & 7);
            int src = ((k >> 7) * 128 + (k & 127)) * 256 + C;
            v = is_sig ? ws[src] : wt[src];
        } else if (row < 768) {
            int j = row - 512;
            v = (j < 128) ? wr[k * 128 + j] : wk[k * 256 + (j - 128)];
        } else {
            v = wk[k * 256 + 128 + (row - 768)];
        }
        int q = (k & ~7) + ((k & 3) << 1) + ((k >> 2) & 1);
        wscratch[row * 256 + q] = __uint_as_float(tf32r(v));
    } else {
        size_t g = (size_t)(bid - 896) * 256 + tid;   // < 2097152
        const float* src = x + g * 8;
        float4 lo = *(const float4*)src;
        float4 hi = *(const float4*)(src + 4);
        float4 o0 = make_float4(__uint_as_float(tf32r(lo.x)), __uint_as_float(tf32r(hi.x)),
                                __uint_as_float(tf32r(lo.y)), __uint_as_float(tf32r(hi.y)));
        float4 o1 = make_float4(__uint_as_float(tf32r(lo.z)), __uint_as_float(tf32r(hi.z)),
                                __uint_as_float(tf32r(lo.w)), __uint_as_float(tf32r(hi.w)));
        float* dst = xscratch + g * 8;
        *(float4*)dst = o0;
        *(float4*)(dst + 4) = o1;
    }
}

// ------------------------------ fused kernel -------------------------------
__global__ void __launch_bounds__(512, 1)
fused_kernel(const float* __restrict__ x,
             const float* __restrict__ bt, const float* __restrict__ bs,
             const float* __restrict__ br, const float* __restrict__ bk,
             float* __restrict__ out) {
    extern __shared__ float sm[];
    uint32_t sb = smaddr(sm);
    int tid = threadIdx.x, wid = tid >> 5, lid = tid & 31;
    int r0 = lid >> 2, c0 = lid & 3;
    int rx3 = r0 & 3;
    int tile = blockIdx.x;
    long g0 = (long)tile * 128;
    bool head = (tile & 127) == 0;          // first tile in a batch row (T=16384)

    float acc[4][4][4];

    // per-thread loader constants
    const int ldb   = tid & 7;              // 16B group within 128B row
    const int ldrow = tid >> 3;             // 0..63
    const uint32_t ldswz = 4u * (uint32_t)(ldb ^ ((ldrow & 3) << 1));

    auto loadA = [&](int kc, int st) {      // 128 rows x 32 k
#pragma unroll
        for (int i = 0; i < 2; ++i) {
            int row = ldrow + i * 64;
            const float* src = xscratch;
            int sz = 16;
            if (kc < 4) {
                if (head && row < 4) sz = 0;
                else src = xscratch + (g0 + row - 4) * 128 + kc * 32 + ldb * 4;
            } else {
                src = xscratch + (g0 + row) * 128 + (kc - 4) * 32 + ldb * 4;
            }
            cpa16(sb + (uint32_t)(AOFF + st * 4096 + row * 32) * 4 + ldswz * 4, src, sz);
        }
    };
    auto loadB256 = [&](const float* wb, int kc, int st) {   // 256 rows
#pragma unroll
        for (int i = 0; i < 4; ++i) {
            int row = ldrow + i * 64;
            const float* src = wb + row * 256 + kc * 32 + ldb * 4;
            cpa16(sb + (uint32_t)(BOFF + st * 8192 + row * 32) * 4 + ldswz * 4, src, 16);
        }
    };
    auto loadB128 = [&](const float* wb, int kc, int st) {   // 128 rows
#pragma unroll
        for (int i = 0; i < 2; ++i) {
            int row = ldrow + i * 64;
            const float* src = wb + row * 256 + kc * 32 + ldb * 4;
            cpa16(sb + (uint32_t)(BOFF + st * 8192 + row * 32) * 4 + ldswz * 4, src, 16);
        }
    };

    auto zacc = [&]() {
#pragma unroll
        for (int i = 0; i < 4; ++i)
#pragma unroll
            for (int j = 0; j < 4; ++j)
#pragma unroll
                for (int q = 0; q < 4; ++q) acc[i][j][q] = 0.f;
    };

    // ---- compute bodies (warp 64x32 for gate/out0; 32x32 for out1) ----
    auto gate_compute = [&](int kc) {
        const float* As = sm + AOFF + (kc & 1) * 4096 + (wid >> 3) * 2048 + r0 * 32;
        const float* Bs = sm + BOFF + (kc & 1) * 8192 + (wid & 7) * 1024 + r0 * 32;
#pragma unroll
        for (int ks = 0; ks < 4; ++ks) {
            int o = ((ks ^ rx3) << 3) + 2 * c0;
            uint32_t a[4][4];
#pragma unroll
            for (int mf = 0; mf < 4; ++mf) {
                float2 lo = *(const float2*)(As + mf * 512 + o);
                float2 hi = *(const float2*)(As + mf * 512 + 256 + o);
                a[mf][0] = __float_as_uint(lo.x); a[mf][1] = __float_as_uint(hi.x);
                a[mf][2] = __float_as_uint(lo.y); a[mf][3] = __float_as_uint(hi.y);
            }
#pragma unroll
            for (int nf = 0; nf < 4; ++nf) {
                float2 bv = *(const float2*)(Bs + nf * 256 + o);
                uint32_t b[2] = {__float_as_uint(bv.x), __float_as_uint(bv.y)};
#pragma unroll
                for (int mf = 0; mf < 4; ++mf) mma8(acc[mf][nf], a[mf], b);
            }
        }
    };
    auto out_compute256 = [&](int kc) {
        const float* Ms = sm + MOFF + (wid >> 3) * 16384 + r0 * 256 + kc * 32;
        const float* Bs = sm + BOFF + (kc & 1) * 8192 + (wid & 7) * 1024 + r0 * 32;
#pragma unroll
        for (int ks = 0; ks < 4; ++ks) {
            int o = ((ks ^ rx3) << 3) + 2 * c0;
            uint32_t a[4][4];
#pragma unroll
            for (int mf = 0; mf < 4; ++mf) {
                float2 lo = *(const float2*)(Ms + mf * 4096 + o);
                float2 hi = *(const float2*)(Ms + mf * 4096 + 2048 + o);
                a[mf][0] = __float_as_uint(lo.x); a[mf][1] = __float_as_uint(hi.x);
                a[mf][2] = __float_as_uint(lo.y); a[mf][3] = __float_as_uint(hi.y);
            }
#pragma unroll
            for (int nf = 0; nf < 4; ++nf) {
                float2 bv = *(const float2*)(Bs + nf * 256 + o);
                uint32_t b[2] = {__float_as_uint(bv.x), __float_as_uint(bv.y)};
#pragma unroll
                for (int mf = 0; mf < 4; ++mf) mma8(acc[mf][nf], a[mf], b);
            }
        }
    };
    auto out_compute128 = [&](int kc) {
        const float* Ms = sm + MOFF + (wid >> 2) * 8192 + r0 * 256 + kc * 32;
        const float* Bs = sm + BOFF + (kc & 1) * 8192 + (wid & 3) * 1024 + r0 * 32;
#pragma unroll
        for (int ks = 0; ks < 4; ++ks) {
            int o = ((ks ^ rx3) << 3) + 2 * c0;
            uint32_t a[2][4];
#pragma unroll
            for (int mf = 0; mf < 2; ++mf) {
                float2 lo = *(const float2*)(Ms + mf * 4096 + o);
                float2 hi = *(const float2*)(Ms + mf * 4096 + 2048 + o);
                a[mf][0] = __float_as_uint(lo.x); a[mf][1] = __float_as_uint(hi.x);
                a[mf][2] = __float_as_uint(lo.y); a[mf][3] = __float_as_uint(hi.y);
            }
#pragma unroll
            for (int nf = 0; nf < 4; ++nf) {
                float2 bv = *(const float2*)(Bs + nf * 256 + o);
                uint32_t b[2] = {__float_as_uint(bv.x), __float_as_uint(bv.y)};
#pragma unroll
                for (int mf = 0; mf < 2; ++mf) mma8(acc[mf][nf], a[mf], b);
            }
        }
    };

    // ---- gate epilogue: m -> smem m region (pass cols p*128..+127) ----
    auto gate_epi = [&](int p) {
        int mwarp = wid >> 3, nwarp = wid & 7;
#pragma unroll
        for (int mf = 0; mf < 4; ++mf) {
            int rA = mwarp * 64 + mf * 16 + r0;
            int xr = (rA & 3) << 3;
            float* m0 = sm + MOFF + rA * 256;
            float* m1 = m0 + 8 * 256;
#pragma unroll
            for (int j = 0; j < 2; ++j) {
                int G = nwarp * 2 + j;
                int chb = p * 128 + G * 8 + 2 * c0;
                float bt0 = __ldg(bt + chb), bt1 = __ldg(bt + chb + 1);
                float bs0 = __ldg(bs + chb), bs1 = __ldg(bs + chb + 1);
                float* At = acc[mf][2 * j];
                float* Ag = acc[mf][2 * j + 1];
                int e0 = 2 * c0, e1 = e0 + 1;
                int q0 = p * 128 + G * 8 + ((e0 & 3) << 1) + (e0 >> 2);
                int q1 = p * 128 + G * 8 + ((e1 & 3) << 1) + (e1 >> 2);
                m0[q0 ^ xr] = gatem(At[0] + bt0, Ag[0] + bs0);
                m0[q1 ^ xr] = gatem(At[1] + bt1, Ag[1] + bs1);
                m1[q0 ^ xr] = gatem(At[2] + bt0, Ag[2] + bs0);
                m1[q1 ^ xr] = gatem(At[3] + bt1, Ag[3] + bs1);
            }
        }
    };

    const float* wg0 = wscratch;
    const float* wg1 = wscratch + 256 * 256;
    const float* wo0 = wscratch + 512 * 256;
    const float* wo1 = wscratch + 768 * 256;
    float* outR = out;                                // res  [131072,128]
    float* outK = out + (size_t)131072 * 128;         // skip [131072,256]

    // ================= gate pass 0 =================
    zacc();
    loadA(0, 0); loadB256(wg0, 0, 0); cpcommit();
    loadA(1, 1); loadB256(wg0, 1, 1); cpcommit();
#pragma unroll 1
    for (int kc = 0; kc < 8; ++kc) {
        CPWAIT(1);
        __syncthreads();
        gate_compute(kc);
        __syncthreads();
        if (kc < 6) { loadA(kc + 2, kc & 1); loadB256(wg0, kc + 2, kc & 1); }
        cpcommit();
    }
    // prefetch pass-1 stages, then do epilogue under their latency
    loadA(0, 0); loadB256(wg1, 0, 0); cpcommit();
    loadA(1, 1); loadB256(wg1, 1, 1); cpcommit();
    gate_epi(0);

    // ================= gate pass 1 =================
    zacc();
#pragma unroll 1
    for (int kc = 0; kc < 8; ++kc) {
        CPWAIT(1);
        __syncthreads();
        gate_compute(kc);
        __syncthreads();
        if (kc < 6) { loadA(kc + 2, kc & 1); loadB256(wg1, kc + 2, kc & 1); }
        cpcommit();
    }
    loadB256(wo0, 0, 0); cpcommit();
    loadB256(wo0, 1, 1); cpcommit();
    gate_epi(1);

    // ================= out pass 0 (res | skip 0..127) =================
    zacc();
#pragma unroll 1
    for (int kc = 0; kc < 8; ++kc) {
        CPWAIT(1);
        __syncthreads();        // first iter also fences m stores
        out_compute256(kc);
        __syncthreads();
        if (kc < 6) loadB256(wo0, kc + 2, kc & 1);
        cpcommit();
    }
    loadB128(wo1, 0, 0); cpcommit();
    loadB128(wo1, 1, 1); cpcommit();
    {
        int mwarp = wid >> 3, nwarp = wid & 7;
#pragma unroll
        for (int mf = 0; mf < 4; ++mf) {
            long row0 = g0 + mwarp * 64 + mf * 16 + r0, row1 = row0 + 8;
#pragma unroll
            for (int nf = 0; nf < 4; ++nf) {
                int pcol = nwarp * 32 + nf * 8 + 2 * c0;
                float* A = acc[mf][nf];
                if (nwarp < 4) {
                    float b0 = __ldg(br + pcol), b1 = __ldg(br + pcol + 1);
                    float2 x0v = *(const float2*)(x + row0 * 128 + pcol);
                    float2 x1v = *(const float2*)(x + row1 * 128 + pcol);
                    *(float2*)(outR + row0 * 128 + pcol) =
                        make_float2(A[0] + b0 + x0v.x, A[1] + b1 + x0v.y);
                    *(float2*)(outR + row1 * 128 + pcol) =
                        make_float2(A[2] + b0 + x1v.x, A[3] + b1 + x1v.y);
                } else {
                    int ck = pcol - 128;
                    float b0 = __ldg(bk + ck), b1 = __ldg(bk + ck + 1);
                    *(float2*)(outK + row0 * 256 + ck) = make_float2(A[0] + b0, A[1] + b1);
                    *(float2*)(outK + row1 * 256 + ck) = make_float2(A[2] + b0, A[3] + b1);
                }
            }
        }
    }

    // ================= out pass 1 (skip 128..255) =================
#pragma unroll
    for (int i = 0; i < 2; ++i)
#pragma unroll
        for (int j = 0; j < 4; ++j)
#pragma unroll
            for (int q = 0; q < 4; ++q) acc[i][j][q] = 0.f;
#pragma unroll 1
    for (int kc = 0; kc < 8; ++kc) {
        CPWAIT(1);
        __syncthreads();
        out_compute128(kc);
        __syncthreads();
        if (kc < 6) loadB128(wo1, kc + 2, kc & 1);
        cpcommit();
    }
    {
        int mw4 = wid >> 2, nw4 = wid & 3;
#pragma unroll
        for (int mf = 0; mf < 2; ++mf) {
            long row0 = g0 + mw4 * 32 + mf * 16 + r0, row1 = row0 + 8;
#pragma unroll
            for (int nf = 0; nf < 4; ++nf) {
                int ck = 128 + nw4 * 32 + nf * 8 + 2 * c0;
                float* A = acc[mf][nf];
                float b0 = __ldg(bk + ck), b1 = __ldg(bk + ck + 1);
                *(float2*)(outK + row0 * 256 + ck) = make_float2(A[0] + b0, A[1] + b1);
                *(float2*)(outK + row1 * 256 + ck) = make_float2(A[2] + b0, A[3] + b1);
            }
        }
    }
}

// ------------------------------- launch ------------------------------------
extern "C" void kernel_launch(void* const* d_in, const int* in_sizes, int n_in,
                              void* d_out, int out_size) {
    const float* x  = (const float*)d_in[0];
    const float* wt = (const float*)d_in[1];
    const float* bt = (const float*)d_in[2];
    const float* ws = (const float*)d_in[3];
    const float* bs = (const float*)d_in[4];
    const float* wr = (const float*)d_in[5];
    const float* br = (const float*)d_in[6];
    const float* wk = (const float*)d_in[7];
    const float* bk = (const float*)d_in[8];
    float* out = (float*)d_out;

    cudaFuncSetAttribute(fused_kernel,
                         cudaFuncAttributeMaxDynamicSharedMemorySize, SMEM_BYTES);

    prep_kernel<<<896 + 8192, 256>>>(wt, ws, wr, wk, x);
    fused_kernel<<<1024, 512, SMEM_BYTES>>>(x, bt, bs, br, bk, out);
}